// round 6
// baseline (speedup 1.0000x reference)
#include <cuda_runtime.h>
#include <math.h>
#include <stdint.h>

// Problem constants
#define BB 256
#define TT 1000
#define NN 200
#define NII 7

#define ALPHA_F 0.2f
#define OMA_F   0.8f
#define NSC_F   0.0948683292f   // 0.15*sqrt(2*0.2)

// packed fp32x2 FMA, W packed in b64
__device__ __forceinline__ void ffma2(unsigned long long& acc, unsigned long long w,
                                      float ylo, float yhi) {
    asm("{\n\t"
        ".reg .b64 yy;\n\t"
        "mov.b64 yy, {%2, %3};\n\t"
        "fma.rn.f32x2 %0, %1, yy, %0;\n\t"
        "}"
        : "+l"(acc) : "l"(w), "f"(ylo), "f"(yhi));
}

__device__ __forceinline__ float hsum4(unsigned long long a, unsigned long long b) {
    unsigned long long s;
    asm("add.rn.f32x2 %0, %1, %2;" : "=l"(s) : "l"(a), "l"(b));
    float2 f;
    asm("mov.b64 {%0, %1}, %2;" : "=f"(f.x), "=f"(f.y) : "l"(s));
    return f.x + f.y;
}

// 4-byte cp.async (LDGSTS): no destination register, pure async prefetch
__device__ __forceinline__ void cpa4(uint32_t dst, const float* src) {
    asm volatile("cp.async.ca.shared.global [%0], [%1], 4;" :: "r"(dst), "l"(src));
}
__device__ __forceinline__ void cpa_commit() {
    asm volatile("cp.async.commit_group;" ::: "memory");
}
__device__ __forceinline__ void cpa_wait1() {
    asm volatile("cp.async.wait_group 1;" ::: "memory");
}

__global__ void __launch_bounds__(256, 1)
rnn_persistent_kernel(const float* __restrict__ y0,
                      const float* __restrict__ u_seq,
                      const float* __restrict__ noise,
                      const float* __restrict__ W_in_raw,
                      const float* __restrict__ W_rec,
                      const float* __restrict__ b_rec,
                      const float* __restrict__ w_out,
                      const float* __restrict__ b_out,
                      float* __restrict__ out)
{
    __shared__ __align__(16) float y_s[2][2][NN];   // [buf][row][neuron]
    __shared__ __align__(16) float nbuf[2][2][NN];  // noise double buffer (cp.async)
    __shared__ float u_s[2][2][NII];                // [buf][row][input]

    const int tid = threadIdx.x;
    const int n   = tid;                 // neuron id; 200 = z; 201..255 aux/idle
    const bool is_neuron = (n <  NN);
    const bool is_z      = (n == NN);
    const bool active    = (n <= NN);
    const int  ut  = tid - 208;          // u-copy duty on dummy lanes 208..221
    const bool is_u = (ut >= 0 && ut < 2 * NII);
    const int  b0 = blockIdx.x * 2;
    const int  b1 = b0 + 1;

    float* __restrict__ y_seq = out;
    float* __restrict__ z_seq = out + (size_t)BB * TT * NN;
    float* __restrict__ y_fin = out + (size_t)BB * TT * NN + (size_t)BB * TT;

    // ---- full W row in registers (200 fp32 = 100 x b64) ----
    unsigned long long w[NN / 2];
    float wia[NII];
    float brec = 0.f, bout = 0.f;
    float yold0 = 0.f, yold1 = 0.f;

    if (active) {
        const float* base = is_z ? w_out : (W_rec + (size_t)n * NN);
        const unsigned long long* wp = reinterpret_cast<const unsigned long long*>(base);
        #pragma unroll
        for (int m = 0; m < NN / 2; ++m) w[m] = __ldg(&wp[m]);
    }
    if (is_neuron) {
        #pragma unroll
        for (int i = 0; i < NII; ++i) wia[i] = fabsf(W_in_raw[n * NII + i]);
        brec  = b_rec[n];
        yold0 = y0[(size_t)b0 * NN + n];
        yold1 = y0[(size_t)b1 * NN + n];
        y_s[0][0][n] = yold0;
        y_s[0][1][n] = yold1;
    }
    if (is_z) bout = b_out[0];
    if (is_u) {
        int bl = ut / NII, i = ut % NII;
        u_s[0][bl][i] = u_seq[(size_t)(b0 + bl) * TT * NII + i];
    }

    // noise source pointers (advance by NN per step); smem dst addresses
    const float* np0 = noise + (size_t)b0 * TT * NN + (is_neuron ? n : 0);
    const float* np1 = noise + (size_t)b1 * TT * NN + (is_neuron ? n : 0);
    const uint32_t nb0_a = (uint32_t)__cvta_generic_to_shared(&nbuf[0][0][is_neuron ? n : 0]);
    const uint32_t nb0_b = (uint32_t)__cvta_generic_to_shared(&nbuf[0][1][is_neuron ? n : 0]);
    const uint32_t nb1_a = (uint32_t)__cvta_generic_to_shared(&nbuf[1][0][is_neuron ? n : 0]);
    const uint32_t nb1_b = (uint32_t)__cvta_generic_to_shared(&nbuf[1][1][is_neuron ? n : 0]);

    // prefetch noise for t=0 into nbuf[0]
    if (is_neuron) { cpa4(nb0_a, np0); cpa4(nb0_b, np1); }
    cpa_commit();

    // incremental output pointers
    float* yp0 = y_seq + (size_t)b0 * TT * NN + (is_neuron ? n : 0);
    float* yp1 = y_seq + (size_t)b1 * TT * NN + (is_neuron ? n : 0);

    __syncthreads();

    int buf = 0;
    for (int t = 0; t < TT; ++t) {
        // ---- async prefetch of next step's noise (no registers consumed) ----
        {
            int t1 = (t + 1 < TT) ? (t + 1) : t;   // clamped; last-iter data unused
            const float* s0 = np0 + (size_t)t1 * NN;
            const float* s1 = np1 + (size_t)t1 * NN;
            if (is_neuron) {
                cpa4(buf ? nb0_a : nb1_a, s0);
                cpa4(buf ? nb0_b : nb1_b, s1);
            }
            cpa_commit();
        }
        // u prefetch on dummy lanes (1 reg, off the neuron critical path)
        float un = 0.f;
        if (is_u && (t + 1 < TT)) {
            int bl = ut / NII, i = ut % NII;
            un = __ldcs(&u_seq[((size_t)(b0 + bl) * TT + (t + 1)) * NII + i]);
        }

        if (active) {
            // ---- dot over y_s[buf]: 4 independent FFMA2 chains ----
            const float4* Y0 = reinterpret_cast<const float4*>(y_s[buf][0]);
            const float4* Y1 = reinterpret_cast<const float4*>(y_s[buf][1]);
            unsigned long long c0a = 0ull, c0b = 0ull, c1a = 0ull, c1b = 0ull;
            #pragma unroll
            for (int m = 0; m < NN / 4; ++m) {
                float4 p = Y0[m];
                float4 q = Y1[m];
                ffma2(c0a, w[2 * m],     p.x, p.y);
                ffma2(c0b, w[2 * m + 1], p.z, p.w);
                ffma2(c1a, w[2 * m],     q.x, q.y);
                ffma2(c1b, w[2 * m + 1], q.z, q.w);
            }
            float pre0 = hsum4(c0a, c0b);
            float pre1 = hsum4(c1a, c1b);

            cpa_wait1();   // noise[t] (copied by THIS thread) now in nbuf[buf]

            if (is_neuron) {
                float dr0 = brec, dr1 = brec;
                #pragma unroll
                for (int i = 0; i < NII; ++i) {
                    dr0 = fmaf(wia[i], u_s[buf][0][i], dr0);
                    dr1 = fmaf(wia[i], u_s[buf][1][i], dr1);
                }
                float nz0 = nbuf[buf][0][n];
                float nz1 = nbuf[buf][1][n];
                float r0 = fmaxf(pre0 + dr0, 0.f);
                float r1 = fmaxf(pre1 + dr1, 0.f);
                float yn0 = fmaf(OMA_F, yold0, fmaf(ALPHA_F, r0, NSC_F * nz0));
                float yn1 = fmaf(OMA_F, yold1, fmaf(ALPHA_F, r1, NSC_F * nz1));
                y_s[buf ^ 1][0][n] = yn0;
                y_s[buf ^ 1][1][n] = yn1;
                __stcs(yp0, yn0);
                __stcs(yp1, yn1);
                yp0 += NN; yp1 += NN;
                yold0 = yn0; yold1 = yn1;
            } else if (t >= 1) {
                // z thread's dot was over y_{t-1}
                z_seq[(size_t)b0 * TT + (t - 1)] = 1.f / (1.f + expf(-(pre0 + bout)));
                z_seq[(size_t)b1 * TT + (t - 1)] = 1.f / (1.f + expf(-(pre1 + bout)));
            }
        } else {
            cpa_wait1();   // keep group bookkeeping uniform
        }
        if (is_u && (t + 1 < TT)) {
            int bl = ut / NII, i = ut % NII;
            u_s[buf ^ 1][bl][i] = un;
        }
        __syncthreads();
        buf ^= 1;
    }

    // ---- tails ----
    if (is_neuron) {
        y_fin[(size_t)b0 * NN + n] = yold0;
        y_fin[(size_t)b1 * NN + n] = yold1;
    }
    if (is_z) {
        const float4* Y0 = reinterpret_cast<const float4*>(y_s[buf][0]);
        const float4* Y1 = reinterpret_cast<const float4*>(y_s[buf][1]);
        unsigned long long c0a = 0ull, c0b = 0ull, c1a = 0ull, c1b = 0ull;
        #pragma unroll
        for (int m = 0; m < NN / 4; ++m) {
            float4 p = Y0[m];
            float4 q = Y1[m];
            ffma2(c0a, w[2 * m],     p.x, p.y);
            ffma2(c0b, w[2 * m + 1], p.z, p.w);
            ffma2(c1a, w[2 * m],     q.x, q.y);
            ffma2(c1b, w[2 * m + 1], q.z, q.w);
        }
        float pre0 = hsum4(c0a, c0b);
        float pre1 = hsum4(c1a, c1b);
        z_seq[(size_t)b0 * TT + (TT - 1)] = 1.f / (1.f + expf(-(pre0 + bout)));
        z_seq[(size_t)b1 * TT + (TT - 1)] = 1.f / (1.f + expf(-(pre1 + bout)));
    }
}

extern "C" void kernel_launch(void* const* d_in, const int* in_sizes, int n_in,
                              void* d_out, int out_size) {
    const float* y0       = (const float*)d_in[0];
    const float* u_seq    = (const float*)d_in[1];
    const float* noise    = (const float*)d_in[2];
    const float* W_in_raw = (const float*)d_in[3];
    const float* W_rec    = (const float*)d_in[4];
    const float* b_rec    = (const float*)d_in[5];
    const float* w_out    = (const float*)d_in[6];
    const float* b_out    = (const float*)d_in[7];
    float* out = (float*)d_out;

    rnn_persistent_kernel<<<BB / 2, 256>>>(y0, u_seq, noise, W_in_raw, W_rec,
                                           b_rec, w_out, b_out, out);
}

// round 8
// speedup vs baseline: 1.0222x; 1.0222x over previous
#include <cuda_runtime.h>
#include <math.h>

// Problem constants
#define BB 256
#define TT 1000
#define NN 200
#define NII 7
#define NSPARE 55            // crew threads: tid 201..255

#define ALPHA_F 0.2f
#define OMA_F   0.8f
#define NSC_F   0.0948683292f   // 0.15*sqrt(2*0.2)

// packed fp32x2 FMA, W packed in b64
__device__ __forceinline__ void ffma2(unsigned long long& acc, unsigned long long w,
                                      float ylo, float yhi) {
    asm("{\n\t"
        ".reg .b64 yy;\n\t"
        "mov.b64 yy, {%2, %3};\n\t"
        "fma.rn.f32x2 %0, %1, yy, %0;\n\t"
        "}"
        : "+l"(acc) : "l"(w), "f"(ylo), "f"(yhi));
}

__device__ __forceinline__ float hsum4(unsigned long long a, unsigned long long b) {
    unsigned long long s;
    asm("add.rn.f32x2 %0, %1, %2;" : "=l"(s) : "l"(a), "l"(b));
    float2 f;
    asm("mov.b64 {%0, %1}, %2;" : "=f"(f.x), "=f"(f.y) : "l"(s));
    return f.x + f.y;
}

__global__ void __launch_bounds__(256, 1)
rnn_persistent_kernel(const float* __restrict__ y0,
                      const float* __restrict__ u_seq,
                      const float* __restrict__ noise,
                      const float* __restrict__ W_in_raw,
                      const float* __restrict__ W_rec,
                      const float* __restrict__ b_rec,
                      const float* __restrict__ w_out,
                      const float* __restrict__ b_out,
                      float* __restrict__ out)
{
    __shared__ __align__(16) float y_s[2][2][NN];   // [buf][row][neuron]
    __shared__ __align__(16) float nsm[2][2][NN];   // noise double buffer
    __shared__ float u_s[2][2][NII];                // [buf][row][input]

    const int tid = threadIdx.x;
    const int n   = tid;                 // 0..199 neurons; 200 z; 201..255 memory crew
    const bool is_neuron = (n <  NN);
    const bool is_z      = (n == NN);
    const bool active    = (n <= NN);
    const int  sid = tid - 201;          // crew id 0..54 (or negative)
    const int  b0 = blockIdx.x * 2;
    const int  b1 = b0 + 1;

    float* __restrict__ y_seq = out;
    float* __restrict__ z_seq = out + (size_t)BB * TT * NN;
    float* __restrict__ y_fin = out + (size_t)BB * TT * NN + (size_t)BB * TT;

    // ---- full W row in registers (200 fp32 = 100 x b64) ----
    unsigned long long w[NN / 2];
    float wia[NII];
    float brec = 0.f, bout = 0.f;
    float yold0 = 0.f, yold1 = 0.f;

    if (active) {
        const float* base = is_z ? w_out : (W_rec + (size_t)n * NN);
        const unsigned long long* wp = reinterpret_cast<const unsigned long long*>(base);
        #pragma unroll
        for (int m = 0; m < NN / 2; ++m) w[m] = __ldg(&wp[m]);
    }
    if (is_neuron) {
        #pragma unroll
        for (int i = 0; i < NII; ++i) wia[i] = fabsf(W_in_raw[n * NII + i]);
        brec  = b_rec[n];
        yold0 = y0[(size_t)b0 * NN + n];
        yold1 = y0[(size_t)b1 * NN + n];
        y_s[0][0][n] = yold0;
        y_s[0][1][n] = yold1;
    }
    if (is_z) bout = b_out[0];

    // crew: preload noise[t=0] (100 float4 over 55 lanes) and u[t=0]
    if (sid >= 0) {
        for (int q = sid; q < 100; q += NSPARE) {
            int row = q / 50, j = q % 50;
            const float4* src = reinterpret_cast<const float4*>(
                noise + (size_t)(b0 + row) * TT * NN) + j;
            reinterpret_cast<float4*>(nsm[0][row])[j] = __ldg(src);
        }
        if (sid >= 41) {   // 14 lanes: u[t=0]
            int q = sid - 41, bl = q / NII, i = q % NII;
            u_s[0][bl][i] = __ldg(&u_seq[(size_t)(b0 + bl) * TT * NII + i]);
        }
    }
    __syncthreads();

    int buf = 0;
    for (int t = 0; t < TT; ++t) {
        if (sid >= 0) {
            // ==== memory crew: drain y[t-1], prefetch noise[t+1], u[t+1] ====
            if (t > 0) {
                #pragma unroll 1
                for (int q = sid; q < 100; q += NSPARE) {
                    int row = q / 50, j = q % 50;
                    float4 v = reinterpret_cast<const float4*>(y_s[buf][row])[j];
                    float4* dst = reinterpret_cast<float4*>(
                        y_seq + ((size_t)(b0 + row) * TT + (t - 1)) * NN) + j;
                    __stcs(dst, v);
                }
            }
            if (t + 1 < TT) {
                #pragma unroll 1
                for (int q = sid; q < 100; q += NSPARE) {
                    int row = q / 50, j = q % 50;
                    const float4* src = reinterpret_cast<const float4*>(
                        noise + ((size_t)(b0 + row) * TT + (t + 1)) * NN) + j;
                    reinterpret_cast<float4*>(nsm[buf ^ 1][row])[j] = __ldcs(src);
                }
                if (sid >= 41) {
                    int q = sid - 41, bl = q / NII, i = q % NII;
                    u_s[buf ^ 1][bl][i] =
                        __ldcs(&u_seq[((size_t)(b0 + bl) * TT + (t + 1)) * NII + i]);
                }
            }
        } else {
            // ==== compute: dot over y_s[buf], 4 independent FFMA2 chains ====
            const float4* Y0 = reinterpret_cast<const float4*>(y_s[buf][0]);
            const float4* Y1 = reinterpret_cast<const float4*>(y_s[buf][1]);
            unsigned long long c0a = 0ull, c0b = 0ull, c1a = 0ull, c1b = 0ull;
            #pragma unroll
            for (int m = 0; m < NN / 4; ++m) {
                float4 p = Y0[m];
                float4 q = Y1[m];
                ffma2(c0a, w[2 * m],     p.x, p.y);
                ffma2(c0b, w[2 * m + 1], p.z, p.w);
                ffma2(c1a, w[2 * m],     q.x, q.y);
                ffma2(c1b, w[2 * m + 1], q.z, q.w);
            }
            float pre0 = hsum4(c0a, c0b);
            float pre1 = hsum4(c1a, c1b);

            if (is_neuron) {
                float dr0 = brec, dr1 = brec;
                #pragma unroll
                for (int i = 0; i < NII; ++i) {
                    dr0 = fmaf(wia[i], u_s[buf][0][i], dr0);
                    dr1 = fmaf(wia[i], u_s[buf][1][i], dr1);
                }
                float nz0 = nsm[buf][0][n];
                float nz1 = nsm[buf][1][n];
                float r0 = fmaxf(pre0 + dr0, 0.f);
                float r1 = fmaxf(pre1 + dr1, 0.f);
                float yn0 = fmaf(OMA_F, yold0, fmaf(ALPHA_F, r0, NSC_F * nz0));
                float yn1 = fmaf(OMA_F, yold1, fmaf(ALPHA_F, r1, NSC_F * nz1));
                y_s[buf ^ 1][0][n] = yn0;
                y_s[buf ^ 1][1][n] = yn1;
                yold0 = yn0; yold1 = yn1;
            } else if (t >= 1) {
                // z thread's dot was over y_{t-1}
                z_seq[(size_t)b0 * TT + (t - 1)] = 1.f / (1.f + expf(-(pre0 + bout)));
                z_seq[(size_t)b1 * TT + (t - 1)] = 1.f / (1.f + expf(-(pre1 + bout)));
            }
        }
        __syncthreads();
        buf ^= 1;
    }

    // ---- tails ----
    if (sid >= 0) {
        // store y[T-1] (now in y_s[buf])
        for (int q = sid; q < 100; q += NSPARE) {
            int row = q / 50, j = q % 50;
            float4 v = reinterpret_cast<const float4*>(y_s[buf][row])[j];
            float4* dst = reinterpret_cast<float4*>(
                y_seq + ((size_t)(b0 + row) * TT + (TT - 1)) * NN) + j;
            __stcs(dst, v);
        }
    }
    if (is_neuron) {
        y_fin[(size_t)b0 * NN + n] = yold0;
        y_fin[(size_t)b1 * NN + n] = yold1;
    }
    if (is_z) {
        const float4* Y0 = reinterpret_cast<const float4*>(y_s[buf][0]);
        const float4* Y1 = reinterpret_cast<const float4*>(y_s[buf][1]);
        unsigned long long c0a = 0ull, c0b = 0ull, c1a = 0ull, c1b = 0ull;
        #pragma unroll
        for (int m = 0; m < NN / 4; ++m) {
            float4 p = Y0[m];
            float4 q = Y1[m];
            ffma2(c0a, w[2 * m],     p.x, p.y);
            ffma2(c0b, w[2 * m + 1], p.z, p.w);
            ffma2(c1a, w[2 * m],     q.x, q.y);
            ffma2(c1b, w[2 * m + 1], q.z, q.w);
        }
        float pre0 = hsum4(c0a, c0b);
        float pre1 = hsum4(c1a, c1b);
        z_seq[(size_t)b0 * TT + (TT - 1)] = 1.f / (1.f + expf(-(pre0 + bout)));
        z_seq[(size_t)b1 * TT + (TT - 1)] = 1.f / (1.f + expf(-(pre1 + bout)));
    }
}

extern "C" void kernel_launch(void* const* d_in, const int* in_sizes, int n_in,
                              void* d_out, int out_size) {
    const float* y0       = (const float*)d_in[0];
    const float* u_seq    = (const float*)d_in[1];
    const float* noise    = (const float*)d_in[2];
    const float* W_in_raw = (const float*)d_in[3];
    const float* W_rec    = (const float*)d_in[4];
    const float* b_rec    = (const float*)d_in[5];
    const float* w_out    = (const float*)d_in[6];
    const float* b_out    = (const float*)d_in[7];
    float* out = (float*)d_out;

    rnn_persistent_kernel<<<BB / 2, 256>>>(y0, u_seq, noise, W_in_raw, W_rec,
                                           b_rec, w_out, b_out, out);
}

// round 9
// speedup vs baseline: 1.6669x; 1.6307x over previous
#include <cuda_runtime.h>
#include <math.h>

// Problem constants
#define BB 256
#define TT 1000
#define NN 200
#define NII 7

#define ALPHA_F 0.2f
#define OMA_F   0.8f
#define NSC_F   0.0948683292f   // 0.15*sqrt(2*0.2)

typedef unsigned long long u64;

// packed fp32x2 FMA, both operands already in b64 register pairs -> no MOVs
__device__ __forceinline__ void ffma2(u64& acc, u64 w, u64 y) {
    asm("fma.rn.f32x2 %0, %1, %2, %0;" : "+l"(acc) : "l"(w), "l"(y));
}

__device__ __forceinline__ float hsum4(u64 a, u64 b) {
    u64 s;
    asm("add.rn.f32x2 %0, %1, %2;" : "=l"(s) : "l"(a), "l"(b));
    float2 f;
    asm("mov.b64 {%0, %1}, %2;" : "=f"(f.x), "=f"(f.y) : "l"(s));
    return f.x + f.y;
}

__global__ void __launch_bounds__(256, 1)
rnn_persistent_kernel(const float* __restrict__ y0,
                      const float* __restrict__ u_seq,
                      const float* __restrict__ noise,
                      const float* __restrict__ W_in_raw,
                      const float* __restrict__ W_rec,
                      const float* __restrict__ b_rec,
                      const float* __restrict__ w_out,
                      const float* __restrict__ b_out,
                      float* __restrict__ out)
{
    __shared__ __align__(16) float y_s[2][2][NN];   // [buf][row][neuron]
    __shared__ float u_s[2][2][NII];                // [buf][row][input]

    const int tid = threadIdx.x;
    const int n   = tid;                 // 0..199 neurons; 200 = z; rest idle
    const bool is_neuron = (n <  NN);
    const bool is_z      = (n == NN);
    const bool active    = (n <= NN);
    const int  b0 = blockIdx.x * 2;
    const int  b1 = b0 + 1;

    float* __restrict__ y_seq = out;
    float* __restrict__ z_seq = out + (size_t)BB * TT * NN;
    float* __restrict__ y_fin = out + (size_t)BB * TT * NN + (size_t)BB * TT;

    // ---- full W row in registers (200 fp32 = 100 x b64) ----
    u64 w[NN / 2];
    float wia[NII];
    float brec = 0.f, bout = 0.f;
    float yold0 = 0.f, yold1 = 0.f;

    if (active) {
        const float* base = is_z ? w_out : (W_rec + (size_t)n * NN);
        const u64* wp = reinterpret_cast<const u64*>(base);
        #pragma unroll
        for (int m = 0; m < NN / 2; ++m) w[m] = __ldg(&wp[m]);
    }
    if (is_neuron) {
        #pragma unroll
        for (int i = 0; i < NII; ++i) wia[i] = fabsf(W_in_raw[n * NII + i]);
        brec  = b_rec[n];
        yold0 = y0[(size_t)b0 * NN + n];
        yold1 = y0[(size_t)b1 * NN + n];
        y_s[0][0][n] = yold0;
        y_s[0][1][n] = yold1;
    }
    if (is_z) bout = b_out[0];
    if (tid < 2 * NII) {
        int bl = tid / NII, i = tid % NII;
        u_s[0][bl][i] = u_seq[(size_t)(b0 + bl) * TT * NII + i];
    }
    // noise for t=0
    float nz0 = 0.f, nz1 = 0.f;
    if (is_neuron) {
        nz0 = noise[(size_t)b0 * TT * NN + n];
        nz1 = noise[(size_t)b1 * TT * NN + n];
    }
    __syncthreads();

    int buf = 0;
    for (int t = 0; t < TT; ++t) {
        // ---- prefetch next step's noise / u ----
        float nz0n = 0.f, nz1n = 0.f, un = 0.f;
        if (is_neuron && (t + 1 < TT)) {
            nz0n = __ldcg(&noise[((size_t)b0 * TT + (t + 1)) * NN + n]);
            nz1n = __ldcg(&noise[((size_t)b1 * TT + (t + 1)) * NN + n]);
        }
        if (tid < 2 * NII && (t + 1 < TT)) {
            int bl = tid / NII, i = tid % NII;
            un = __ldcg(&u_seq[((size_t)(b0 + bl) * TT + (t + 1)) * NII + i]);
        }

        if (active) {
            // ---- dot: y loaded as b64 pairs -> FFMA2 with zero operand MOVs ----
            const ulonglong2* Y0 = reinterpret_cast<const ulonglong2*>(y_s[buf][0]);
            const ulonglong2* Y1 = reinterpret_cast<const ulonglong2*>(y_s[buf][1]);
            u64 c0a = 0ull, c0b = 0ull, c1a = 0ull, c1b = 0ull;
            #pragma unroll
            for (int m = 0; m < NN / 4; ++m) {       // 50 iters: 2 LDS.128 + 4 FFMA2
                ulonglong2 p = Y0[m];
                ulonglong2 q = Y1[m];
                ffma2(c0a, w[2 * m],     p.x);
                ffma2(c0b, w[2 * m + 1], p.y);
                ffma2(c1a, w[2 * m],     q.x);
                ffma2(c1b, w[2 * m + 1], q.y);
            }
            float pre0 = hsum4(c0a, c0b);
            float pre1 = hsum4(c1a, c1b);

            if (is_neuron) {
                float dr0 = brec, dr1 = brec;
                #pragma unroll
                for (int i = 0; i < NII; ++i) {
                    dr0 = fmaf(wia[i], u_s[buf][0][i], dr0);
                    dr1 = fmaf(wia[i], u_s[buf][1][i], dr1);
                }
                float r0 = fmaxf(pre0 + dr0, 0.f);
                float r1 = fmaxf(pre1 + dr1, 0.f);
                float yn0 = fmaf(OMA_F, yold0, fmaf(ALPHA_F, r0, NSC_F * nz0));
                float yn1 = fmaf(OMA_F, yold1, fmaf(ALPHA_F, r1, NSC_F * nz1));
                y_s[buf ^ 1][0][n] = yn0;
                y_s[buf ^ 1][1][n] = yn1;
                __stcs(&y_seq[((size_t)b0 * TT + t) * NN + n], yn0);
                __stcs(&y_seq[((size_t)b1 * TT + t) * NN + n], yn1);
                yold0 = yn0; yold1 = yn1;
                nz0 = nz0n; nz1 = nz1n;
            } else if (t >= 1) {
                // z thread's dot was over y_{t-1}
                z_seq[(size_t)b0 * TT + (t - 1)] = 1.f / (1.f + expf(-(pre0 + bout)));
                z_seq[(size_t)b1 * TT + (t - 1)] = 1.f / (1.f + expf(-(pre1 + bout)));
            }
        }
        if (tid < 2 * NII && (t + 1 < TT)) {
            int bl = tid / NII, i = tid % NII;
            u_s[buf ^ 1][bl][i] = un;
        }
        __syncthreads();
        buf ^= 1;
    }

    // ---- tails ----
    if (is_neuron) {
        y_fin[(size_t)b0 * NN + n] = yold0;
        y_fin[(size_t)b1 * NN + n] = yold1;
    }
    if (is_z) {
        const ulonglong2* Y0 = reinterpret_cast<const ulonglong2*>(y_s[buf][0]);
        const ulonglong2* Y1 = reinterpret_cast<const ulonglong2*>(y_s[buf][1]);
        u64 c0a = 0ull, c0b = 0ull, c1a = 0ull, c1b = 0ull;
        #pragma unroll
        for (int m = 0; m < NN / 4; ++m) {
            ulonglong2 p = Y0[m];
            ulonglong2 q = Y1[m];
            ffma2(c0a, w[2 * m],     p.x);
            ffma2(c0b, w[2 * m + 1], p.y);
            ffma2(c1a, w[2 * m],     q.x);
            ffma2(c1b, w[2 * m + 1], q.y);
        }
        float pre0 = hsum4(c0a, c0b);
        float pre1 = hsum4(c1a, c1b);
        z_seq[(size_t)b0 * TT + (TT - 1)] = 1.f / (1.f + expf(-(pre0 + bout)));
        z_seq[(size_t)b1 * TT + (TT - 1)] = 1.f / (1.f + expf(-(pre1 + bout)));
    }
}

extern "C" void kernel_launch(void* const* d_in, const int* in_sizes, int n_in,
                              void* d_out, int out_size) {
    const float* y0       = (const float*)d_in[0];
    const float* u_seq    = (const float*)d_in[1];
    const float* noise    = (const float*)d_in[2];
    const float* W_in_raw = (const float*)d_in[3];
    const float* W_rec    = (const float*)d_in[4];
    const float* b_rec    = (const float*)d_in[5];
    const float* w_out    = (const float*)d_in[6];
    const float* b_out    = (const float*)d_in[7];
    float* out = (float*)d_out;

    rnn_persistent_kernel<<<BB / 2, 256>>>(y0, u_seq, noise, W_in_raw, W_rec,
                                           b_rec, w_out, b_out, out);
}